// round 3
// baseline (speedup 1.0000x reference)
#include <cuda_runtime.h>
#include <cuda_bf16.h>

// Cross-head online Hadamard: for each (token, d) with d in [0,128),
// apply a 32-point Walsh-Hadamard transform (Sylvester order) across the
// 32 heads, scale by 1/sqrt(32).
//
// Layout: x[t * 4096 + h * 128 + d]. A warp's 32 lanes cover consecutive d,
// so each of the 32 per-thread loads/stores is a contiguous 128B warp
// transaction. Butterfly is entirely in registers (32 floats/thread).

#define HIDDEN    4096
#define NUM_HEADS 32
#define HEAD_DIM  128
#define TOK_PER_BLOCK 2   // 256 threads = 2 tokens * 128 dims

__global__ __launch_bounds__(TOK_PER_BLOCK * HEAD_DIM, 8)
void cross_head_hadamard_kernel(const float* __restrict__ x,
                                float* __restrict__ y,
                                int num_tokens)
{
    const int local_tok = threadIdx.x >> 7;          // 0..TOK_PER_BLOCK-1
    const int d         = threadIdx.x & (HEAD_DIM - 1);
    const long long t   = (long long)blockIdx.x * TOK_PER_BLOCK + local_tok;
    if (t >= num_tokens) return;

    const float* __restrict__ p = x + t * HIDDEN + d;
    float* __restrict__       q = y + t * HIDDEN + d;

    float v[NUM_HEADS];

    // Front-batched loads: 32 independent LDGs -> MLP ~32, hides DRAM latency.
    #pragma unroll
    for (int h = 0; h < NUM_HEADS; ++h)
        v[h] = p[h * HEAD_DIM];

    // In-place FWHT, 5 stages. Equivalent to the reference's stack butterfly
    // (Sylvester-ordered Hadamard): out[j] = sum_i (-1)^popc(i&j) * in[i].
    #pragma unroll
    for (int s = 1; s < NUM_HEADS; s <<= 1) {
        #pragma unroll
        for (int i = 0; i < NUM_HEADS; ++i) {
            if ((i & s) == 0) {
                const float a = v[i];
                const float b = v[i + s];
                v[i]     = a + b;
                v[i + s] = a - b;
            }
        }
    }

    // 1/sqrt(32), matching float32 scaling in the reference.
    const float scale = 0.17677669529663687f;

    #pragma unroll
    for (int h = 0; h < NUM_HEADS; ++h)
        q[h * HEAD_DIM] = v[h] * scale;
}

extern "C" void kernel_launch(void* const* d_in, const int* in_sizes, int n_in,
                              void* d_out, int out_size)
{
    const float* x = (const float*)d_in[0];
    float*       y = (float*)d_out;

    const int total_elems = in_sizes[0];           // 4*4096*4096 = 67,108,864
    const int num_tokens  = total_elems / HIDDEN;  // 16384

    const int threads = TOK_PER_BLOCK * HEAD_DIM;  // 256
    const int blocks  = (num_tokens + TOK_PER_BLOCK - 1) / TOK_PER_BLOCK;

    cross_head_hadamard_kernel<<<blocks, threads>>>(x, y, num_tokens);
}

// round 4
// speedup vs baseline: 1.0471x; 1.0471x over previous
#include <cuda_runtime.h>
#include <cuda_bf16.h>

// Cross-head online Hadamard, float2-vectorized.
// For each (token, d-pair), apply a 32-point Walsh-Hadamard transform
// across the 32 heads (stride 128 floats), scale by 1/sqrt(32).
//
// Layout: x[t * 4096 + h * 128 + d]. 64 threads per token, each owning
// 2 adjacent d values -> every per-head access is a 256B LDG.64/STG.64
// warp transaction, fully coalesced. Butterfly entirely in registers.

#define HIDDEN    4096
#define NUM_HEADS 32
#define HEAD_DIM  128
#define VEC       2
#define THR_PER_TOK (HEAD_DIM / VEC)   // 64
#define TOK_PER_BLOCK 4                // 256 threads

__global__ __launch_bounds__(TOK_PER_BLOCK * THR_PER_TOK, 3)
void cross_head_hadamard_f2_kernel(const float2* __restrict__ x,
                                   float2* __restrict__ y,
                                   int num_tokens)
{
    const int local_tok = threadIdx.x >> 6;              // /64
    const int d2        = threadIdx.x & (THR_PER_TOK-1); // 0..63 (float2 index)
    const long long t   = (long long)blockIdx.x * TOK_PER_BLOCK + local_tok;
    if (t >= num_tokens) return;

    const long long base = t * (HIDDEN / VEC) + d2;      // float2 units
    const float2* __restrict__ p = x + base;
    float2* __restrict__       q = y + base;

    float2 v[NUM_HEADS];

    // Front-batched streaming loads: 32 independent LDG.64 -> MLP 32.
    #pragma unroll
    for (int h = 0; h < NUM_HEADS; ++h)
        v[h] = __ldcs(p + h * (HEAD_DIM / VEC));

    // In-place FWHT over heads, 5 stages (Sylvester order):
    // out[j] = sum_i (-1)^popc(i&j) * in[i]
    #pragma unroll
    for (int s = 1; s < NUM_HEADS; s <<= 1) {
        #pragma unroll
        for (int i = 0; i < NUM_HEADS; ++i) {
            if ((i & s) == 0) {
                const float2 a = v[i];
                const float2 b = v[i + s];
                v[i].x     = a.x + b.x;
                v[i].y     = a.y + b.y;
                v[i + s].x = a.x - b.x;
                v[i + s].y = a.y - b.y;
            }
        }
    }

    const float scale = 0.17677669529663687f;  // 1/sqrt(32)

    #pragma unroll
    for (int h = 0; h < NUM_HEADS; ++h) {
        float2 r;
        r.x = v[h].x * scale;
        r.y = v[h].y * scale;
        __stcs(q + h * (HEAD_DIM / VEC), r);
    }
}

extern "C" void kernel_launch(void* const* d_in, const int* in_sizes, int n_in,
                              void* d_out, int out_size)
{
    const float2* x = (const float2*)d_in[0];
    float2*       y = (float2*)d_out;

    const int total_elems = in_sizes[0];           // 67,108,864
    const int num_tokens  = total_elems / HIDDEN;  // 16384

    const int threads = TOK_PER_BLOCK * THR_PER_TOK;  // 256
    const int blocks  = (num_tokens + TOK_PER_BLOCK - 1) / TOK_PER_BLOCK;

    cross_head_hadamard_f2_kernel<<<blocks, threads>>>(x, y, num_tokens);
}